// round 1
// baseline (speedup 1.0000x reference)
#include <cuda_runtime.h>

#define NB      16384
#define OBS     64
#define HD      128
#define NNB     4
#define NNODE   5
#define HEADS   2
#define NACT    8
#define SLOPE   0.2f
#define BT      16
#define NTHREADS 256
#define NROWS   (BT*NNODE)   // 80

// ---- shared memory layout (float offsets) ----
#define OFF_A   0
#define SZ_A    (NROWS*HD)        // 10240: allobs -> emb
#define OFF_B   (OFF_A + SZ_A)
#define SZ_B    (NROWS*HD)        // 10240: hidden -> Wh -> hv/hp
#define OFF_W   (OFF_B + SZ_B)
#define SZ_W    (HD*HD)           // 16384: big weight buffer
#define OFF_W1  (OFF_W + SZ_W)
#define SZ_W1   (OBS*HD)          // 8192: enc_w1
#define OFF_F   (OFF_W1 + SZ_W1)
#define SZ_F    (BT*2*HD)         // 4096: final [16][256]
#define OFF_SM  (OFF_F + SZ_F)
// small: 0 enc_b1[128], 128 enc_b2[128], 256 gat_a[512], 768 val_b1[128],
//        896 val_w2[128], 1024 pol_b1[128], 1152 pol_w2[1024],
//        2176 attn[80], 2256 val_b2, 2257..2264 pol_b2
#define SZ_SM   2272
#define SMEM_FLOATS (OFF_SM + SZ_SM)
#define SMEM_BYTES  (SMEM_FLOATS*4)

// C[80][128] = A[80][K] @ W[K][128] (+bias)(relu). A,W,C in smem.
// 10x4 register tile per thread; float4 loads on both operands.
template<int K>
__device__ __forceinline__ void gemm80(const float* __restrict__ A,
                                       const float* __restrict__ W,
                                       float* __restrict__ C,
                                       const float* __restrict__ bias,
                                       bool do_relu, int tid)
{
    const int tx = tid & 31, ty = tid >> 5;
    const int c0 = tx * 4, r0 = ty * 10;
    float acc[10][4];
    #pragma unroll
    for (int i = 0; i < 10; i++)
        #pragma unroll
        for (int j = 0; j < 4; j++) acc[i][j] = 0.f;

    for (int k = 0; k < K; k += 4) {
        float areg[10][4];
        #pragma unroll
        for (int i = 0; i < 10; i++) {
            const float4 t = *reinterpret_cast<const float4*>(A + (r0+i)*K + k);
            areg[i][0] = t.x; areg[i][1] = t.y; areg[i][2] = t.z; areg[i][3] = t.w;
        }
        #pragma unroll
        for (int kk = 0; kk < 4; kk++) {
            const float4 w = *reinterpret_cast<const float4*>(W + (k+kk)*HD + c0);
            #pragma unroll
            for (int i = 0; i < 10; i++) {
                const float a = areg[i][kk];
                acc[i][0] = fmaf(a, w.x, acc[i][0]);
                acc[i][1] = fmaf(a, w.y, acc[i][1]);
                acc[i][2] = fmaf(a, w.z, acc[i][2]);
                acc[i][3] = fmaf(a, w.w, acc[i][3]);
            }
        }
    }
    float4 bb = make_float4(0.f, 0.f, 0.f, 0.f);
    if (bias) bb = *reinterpret_cast<const float4*>(bias + c0);
    #pragma unroll
    for (int i = 0; i < 10; i++) {
        float4 o;
        o.x = acc[i][0] + bb.x; o.y = acc[i][1] + bb.y;
        o.z = acc[i][2] + bb.z; o.w = acc[i][3] + bb.w;
        if (do_relu) {
            o.x = fmaxf(o.x, 0.f); o.y = fmaxf(o.y, 0.f);
            o.z = fmaxf(o.z, 0.f); o.w = fmaxf(o.w, 0.f);
        }
        *reinterpret_cast<float4*>(C + (r0+i)*HD + c0) = o;
    }
}

// acc[2][4] += F[16][256] chunk (kOff..kOff+128) @ W[128][128]
__device__ __forceinline__ void gemm16_acc(const float* __restrict__ F,
                                           const float* __restrict__ W,
                                           float acc[2][4], int kOff, int tid)
{
    const int tx = tid & 31, ty = tid >> 5;
    const int c0 = tx * 4, r0 = ty * 2;
    for (int k = 0; k < HD; k += 4) {
        const float4 t0 = *reinterpret_cast<const float4*>(F + r0*(2*HD) + kOff + k);
        const float4 t1 = *reinterpret_cast<const float4*>(F + (r0+1)*(2*HD) + kOff + k);
        float a0[4] = {t0.x, t0.y, t0.z, t0.w};
        float a1[4] = {t1.x, t1.y, t1.z, t1.w};
        #pragma unroll
        for (int kk = 0; kk < 4; kk++) {
            const float4 w = *reinterpret_cast<const float4*>(W + (k+kk)*HD + c0);
            acc[0][0] = fmaf(a0[kk], w.x, acc[0][0]);
            acc[0][1] = fmaf(a0[kk], w.y, acc[0][1]);
            acc[0][2] = fmaf(a0[kk], w.z, acc[0][2]);
            acc[0][3] = fmaf(a0[kk], w.w, acc[0][3]);
            acc[1][0] = fmaf(a1[kk], w.x, acc[1][0]);
            acc[1][1] = fmaf(a1[kk], w.y, acc[1][1]);
            acc[1][2] = fmaf(a1[kk], w.z, acc[1][2]);
            acc[1][3] = fmaf(a1[kk], w.w, acc[1][3]);
        }
    }
}

extern "C" __global__ void __launch_bounds__(NTHREADS, 1)
colight(const float* __restrict__ obs, const float* __restrict__ nobs,
        const int* __restrict__ adj,
        const float* __restrict__ enc_w1, const float* __restrict__ enc_b1,
        const float* __restrict__ enc_w2, const float* __restrict__ enc_b2,
        const float* __restrict__ gat_w, const float* __restrict__ gat_a,
        const float* __restrict__ val_w1, const float* __restrict__ val_b1,
        const float* __restrict__ val_w2, const float* __restrict__ val_b2,
        const float* __restrict__ pol_w1, const float* __restrict__ pol_b1,
        const float* __restrict__ pol_w2, const float* __restrict__ pol_b2,
        float* __restrict__ out)
{
    extern __shared__ float sm[];
    float* sA  = sm + OFF_A;
    float* sB  = sm + OFF_B;
    float* sW  = sm + OFF_W;
    float* sW1 = sm + OFF_W1;
    float* sF  = sm + OFF_F;
    float* sSm = sm + OFF_SM;

    const int tid = threadIdx.x;
    const int b0  = blockIdx.x * BT;
    const int wid = tid >> 5, lane = tid & 31;

    // ---------- load inputs + encoder weights ----------
    for (int idx = tid; idx < NROWS*OBS; idx += NTHREADS) {
        const int r = idx >> 6, k = idx & 63;
        const int lb = r / NNODE, n = r - lb*NNODE;
        sA[idx] = (n == 0) ? obs[(size_t)(b0+lb)*OBS + k]
                           : nobs[((size_t)(b0+lb)*NNB + (n-1))*OBS + k];
    }
    for (int idx = tid; idx < OBS*HD; idx += NTHREADS) sW1[idx] = enc_w1[idx];
    for (int idx = tid; idx < HD*HD;  idx += NTHREADS) sW[idx]  = enc_w2[idx];
    for (int idx = tid; idx < HD; idx += NTHREADS) {
        sSm[idx]        = enc_b1[idx];
        sSm[128 + idx]  = enc_b2[idx];
        sSm[768 + idx]  = val_b1[idx];
        sSm[896 + idx]  = val_w2[idx];
        sSm[1024 + idx] = pol_b1[idx];
    }
    for (int idx = tid; idx < 512;  idx += NTHREADS) sSm[256 + idx]  = gat_a[idx];
    for (int idx = tid; idx < 1024; idx += NTHREADS) sSm[1152 + idx] = pol_w2[idx];
    if (tid == 0) sSm[2256] = val_b2[0];
    if (tid < NACT) sSm[2257 + tid] = pol_b2[tid];
    __syncthreads();

    // ---------- encoder: hidden = relu(allobs@W1+b1); emb = hidden@W2+b2 ----------
    gemm80<OBS>(sA, sW1, sB, sSm, true, tid);          // sB = hidden
    __syncthreads();
    gemm80<HD>(sB, sW, sA, sSm + 128, false, tid);     // sA = emb

    // ---------- GAT heads ----------
    for (int h = 0; h < HEADS; h++) {
        __syncthreads();
        for (int idx = tid; idx < HD*HD; idx += NTHREADS) sW[idx] = gat_w[h*HD*HD + idx];
        __syncthreads();
        gemm80<HD>(sA, sW, sB, nullptr, false, tid);   // sB = Wh[h]
        __syncthreads();

        // attention: each warp handles 2 local batch elements
        #pragma unroll
        for (int q = 0; q < 2; q++) {
            const int lb = wid*2 + q;
            const float* a1 = sSm + 256 + h*256;
            const float* a2 = a1 + HD;
            float ei = 0.f, ej0 = 0.f, ej1 = 0.f, ej2 = 0.f, ej3 = 0.f, ej4 = 0.f;
            #pragma unroll
            for (int kk = lane; kk < HD; kk += 32) {
                const float w1v = a1[kk], w2v = a2[kk];
                const float* whb = sB + (lb*NNODE)*HD + kk;
                const float v0 = whb[0*HD], v1 = whb[1*HD], v2 = whb[2*HD],
                            v3 = whb[3*HD], v4 = whb[4*HD];
                ei  = fmaf(v0, w1v, ei);
                ej0 = fmaf(v0, w2v, ej0);
                ej1 = fmaf(v1, w2v, ej1);
                ej2 = fmaf(v2, w2v, ej2);
                ej3 = fmaf(v3, w2v, ej3);
                ej4 = fmaf(v4, w2v, ej4);
            }
            #pragma unroll
            for (int off = 16; off > 0; off >>= 1) {
                ei  += __shfl_xor_sync(0xffffffffu, ei,  off);
                ej0 += __shfl_xor_sync(0xffffffffu, ej0, off);
                ej1 += __shfl_xor_sync(0xffffffffu, ej1, off);
                ej2 += __shfl_xor_sync(0xffffffffu, ej2, off);
                ej3 += __shfl_xor_sync(0xffffffffu, ej3, off);
                ej4 += __shfl_xor_sync(0xffffffffu, ej4, off);
            }
            if (lane == 0) {
                float ej[5] = {ej0, ej1, ej2, ej3, ej4};
                float ev[5];
                float m = -1e30f;
                #pragma unroll
                for (int n = 0; n < NNODE; n++) {
                    const int a = adj[(size_t)(b0+lb)*NNODE + n];
                    if (a != 0) {
                        float e = ei + ej[n];
                        e = (e >= 0.f) ? e : SLOPE * e;
                        ev[n] = e;
                        m = fmaxf(m, e);
                    } else {
                        ev[n] = -1e30f;
                    }
                }
                float s = 0.f;
                #pragma unroll
                for (int n = 0; n < NNODE; n++) {
                    const float p = (ev[n] > -1e29f) ? __expf(ev[n] - m) : 0.f;
                    ev[n] = p; s += p;
                }
                const float inv = 1.f / s;
                #pragma unroll
                for (int n = 0; n < NNODE; n++) sSm[2176 + lb*NNODE + n] = ev[n] * inv;
            }
        }
        __syncthreads();

        // h_prime row 0 -> final[:, h*128:(h+1)*128]
        for (int idx = tid; idx < BT*HD; idx += NTHREADS) {
            const int lb = idx >> 7, c = idx & 127;
            const float* at  = sSm + 2176 + lb*NNODE;
            const float* whb = sB + lb*NNODE*HD + c;
            float s = at[0] * whb[0];
            s = fmaf(at[1], whb[1*HD], s);
            s = fmaf(at[2], whb[2*HD], s);
            s = fmaf(at[3], whb[3*HD], s);
            s = fmaf(at[4], whb[4*HD], s);
            sF[lb*(2*HD) + h*HD + c] = s;
        }
    }
    __syncthreads();

    const int tx = tid & 31, ty = tid >> 5;
    const int c0 = tx * 4, r0 = ty * 2;

    // ---------- value head ----------
    {
        float acc[2][4] = {{0.f,0.f,0.f,0.f},{0.f,0.f,0.f,0.f}};
        for (int ch = 0; ch < 2; ch++) {
            for (int idx = tid; idx < HD*HD; idx += NTHREADS) sW[idx] = val_w1[ch*HD*HD + idx];
            __syncthreads();
            gemm16_acc(sF, sW, acc, ch*HD, tid);
            __syncthreads();
        }
        const float4 bb = *reinterpret_cast<const float4*>(sSm + 768 + c0);
        #pragma unroll
        for (int i = 0; i < 2; i++) {
            float4 o;
            o.x = fmaxf(acc[i][0] + bb.x, 0.f);
            o.y = fmaxf(acc[i][1] + bb.y, 0.f);
            o.z = fmaxf(acc[i][2] + bb.z, 0.f);
            o.w = fmaxf(acc[i][3] + bb.w, 0.f);
            *reinterpret_cast<float4*>(sB + (r0+i)*HD + c0) = o;   // hv
        }
    }
    __syncthreads();
    // value = hv @ val_w2 + val_b2  (warp per 2 batch items)
    #pragma unroll
    for (int q = 0; q < 2; q++) {
        const int lb = wid*2 + q;
        float s = 0.f;
        #pragma unroll
        for (int kk = lane; kk < HD; kk += 32)
            s = fmaf(sB[lb*HD + kk], sSm[896 + kk], s);
        #pragma unroll
        for (int off = 16; off > 0; off >>= 1) s += __shfl_xor_sync(0xffffffffu, s, off);
        if (lane == 0) out[b0 + lb] = s + sSm[2256];
    }
    __syncthreads();

    // ---------- policy head ----------
    {
        float acc[2][4] = {{0.f,0.f,0.f,0.f},{0.f,0.f,0.f,0.f}};
        for (int ch = 0; ch < 2; ch++) {
            for (int idx = tid; idx < HD*HD; idx += NTHREADS) sW[idx] = pol_w1[ch*HD*HD + idx];
            __syncthreads();
            gemm16_acc(sF, sW, acc, ch*HD, tid);
            __syncthreads();
        }
        const float4 bb = *reinterpret_cast<const float4*>(sSm + 1024 + c0);
        #pragma unroll
        for (int i = 0; i < 2; i++) {
            float4 o;
            o.x = fmaxf(acc[i][0] + bb.x, 0.f);
            o.y = fmaxf(acc[i][1] + bb.y, 0.f);
            o.z = fmaxf(acc[i][2] + bb.z, 0.f);
            o.w = fmaxf(acc[i][3] + bb.w, 0.f);
            *reinterpret_cast<float4*>(sB + (r0+i)*HD + c0) = o;   // hp
        }
    }
    __syncthreads();
    // logits = hp @ pol_w2 + pol_b2
    if (tid < BT*NACT) {
        const int lb = tid >> 3, a = tid & 7;
        float s = 0.f;
        for (int kk = 0; kk < HD; kk++)
            s = fmaf(sB[lb*HD + kk], sSm[1152 + kk*NACT + a], s);
        out[NB + (size_t)(b0+lb)*NACT + a] = s + sSm[2257 + a];
    }
}

extern "C" void kernel_launch(void* const* d_in, const int* in_sizes, int n_in,
                              void* d_out, int out_size)
{
    (void)in_sizes; (void)n_in; (void)out_size;
    cudaFuncSetAttribute(colight, cudaFuncAttributeMaxDynamicSharedMemorySize, SMEM_BYTES);
    colight<<<NB/BT, NTHREADS, SMEM_BYTES>>>(
        (const float*)d_in[0],  (const float*)d_in[1],  (const int*)d_in[2],
        (const float*)d_in[3],  (const float*)d_in[4],  (const float*)d_in[5],
        (const float*)d_in[6],  (const float*)d_in[7],  (const float*)d_in[8],
        (const float*)d_in[9],  (const float*)d_in[10], (const float*)d_in[11],
        (const float*)d_in[12], (const float*)d_in[13], (const float*)d_in[14],
        (const float*)d_in[15], (const float*)d_in[16],
        (float*)d_out);
}

// round 2
// speedup vs baseline: 1.1292x; 1.1292x over previous
#include <cuda_runtime.h>

#define NB      16384
#define OBS     64
#define HD      128
#define NNB     4
#define NNODE   5
#define NACT    8
#define SLOPE   0.2f
#define BT      16
#define NTHREADS 256
#define NROWS   (BT*NNODE)   // 80
#define ATS     82           // padded stride for transposed activations (even, ~coprime to 32)
#define FTS     18           // padded stride for final^T [256][16+pad]

typedef unsigned long long u64;

// ---- smem layout (float offsets) ----
#define OFF_B0  0
#define SZ_B0   (HD*ATS)          // 10496
#define OFF_B1  (OFF_B0 + SZ_B0)
#define SZ_B1   (HD*ATS)          // 10496
#define OFF_FT  (OFF_B1 + SZ_B1)
#define SZ_FT   (2*HD*FTS)        // 4608
#define OFF_SM  (OFF_FT + SZ_FT)
// 0 enc_b1[128], 128 enc_b2[128], 256 gat_a[512], 768 val_b1[128],
// 896 val_w2[128], 1024 pol_b1[128], 1152 pol_w2[1024], 2176 attn[80],
// 2256 val_b2, 2257..2264 pol_b2
#define SZ_SM   2272
#define OFF_ADJ (OFF_SM + SZ_SM)  // 80 ints
#define SMEM_FLOATS (OFF_ADJ + 80)
#define SMEM_BYTES  (SMEM_FLOATS*4)

__device__ __forceinline__ u64 ffma2(u64 a, u64 b, u64 c) {
    u64 d;
    asm("fma.rn.f32x2 %0, %1, %2, %3;" : "=l"(d) : "l"(a), "l"(b), "l"(c));
    return d;
}
__device__ __forceinline__ u64 pack2(float x, float y) {
    u64 r; asm("mov.b64 %0, {%1, %2};" : "=l"(r) : "f"(x), "f"(y)); return r;
}
__device__ __forceinline__ float2 unpack2(u64 v) {
    float2 r; asm("mov.b64 {%0, %1}, %2;" : "=f"(r.x), "=f"(r.y) : "l"(v)); return r;
}

// Prefetch nfloats of gmem into L1 (128B lines, strided over the CTA).
__device__ __forceinline__ void pf_l1(const float* p, int tid, int nfloats) {
    for (int off = tid * 32; off < nfloats; off += NTHREADS * 32)
        asm volatile("prefetch.global.L1 [%0];" :: "l"(p + off));
}

// C^T[128][ATS] = (A^T[K][ATS])-gemm: C[r][c] = sum_k A[r][k]*W[k][c] (+bias)(relu).
// A^T in smem (AT[k*ATS + r]); W row-major [K][128] in GLOBAL (read via L1).
// Per-thread tile: 5 row-pairs x 4 cols, f32x2 lanes = (row, row+1).
template<int K, bool RELU>
__device__ __forceinline__ void gemmT(const float* __restrict__ AT,
                                      const float* __restrict__ Wg,
                                      float* __restrict__ CT,
                                      const float* bias,          // smem or nullptr
                                      const float* __restrict__ pf, int pfN,
                                      int tid)
{
    const int tx = tid & 31, ty = tid >> 5;
    const int c0 = tx * 4, r0 = ty * 10;

    if (pf) pf_l1(pf, tid, pfN);

    u64 acc[5][4];
    #pragma unroll
    for (int p = 0; p < 5; p++)
        #pragma unroll
        for (int j = 0; j < 4; j++) acc[p][j] = 0ull;

    #pragma unroll 2
    for (int k = 0; k < K; k++) {
        const float4 w4 = __ldg(reinterpret_cast<const float4*>(Wg + k*HD + c0));
        const u64 w0 = pack2(w4.x, w4.x), w1 = pack2(w4.y, w4.y),
                  w2 = pack2(w4.z, w4.z), w3 = pack2(w4.w, w4.w);
        const float* a = AT + k*ATS + r0;
        u64 a2[5];
        #pragma unroll
        for (int p = 0; p < 5; p++)
            a2[p] = *reinterpret_cast<const u64*>(a + 2*p);
        #pragma unroll
        for (int p = 0; p < 5; p++) {
            acc[p][0] = ffma2(a2[p], w0, acc[p][0]);
            acc[p][1] = ffma2(a2[p], w1, acc[p][1]);
            acc[p][2] = ffma2(a2[p], w2, acc[p][2]);
            acc[p][3] = ffma2(a2[p], w3, acc[p][3]);
        }
    }
    #pragma unroll
    for (int j = 0; j < 4; j++) {
        const float b = bias ? bias[c0 + j] : 0.f;
        #pragma unroll
        for (int p = 0; p < 5; p++) {
            float2 v = unpack2(acc[p][j]);
            v.x += b; v.y += b;
            if (RELU) { v.x = fmaxf(v.x, 0.f); v.y = fmaxf(v.y, 0.f); }
            *reinterpret_cast<float2*>(CT + (c0 + j)*ATS + r0 + 2*p) = v;
        }
    }
}

extern "C" __global__ void __launch_bounds__(NTHREADS, 1)
colight(const float* __restrict__ obs, const float* __restrict__ nobs,
        const int* __restrict__ adj,
        const float* __restrict__ enc_w1, const float* __restrict__ enc_b1,
        const float* __restrict__ enc_w2, const float* __restrict__ enc_b2,
        const float* __restrict__ gat_w, const float* __restrict__ gat_a,
        const float* __restrict__ val_w1, const float* __restrict__ val_b1,
        const float* __restrict__ val_w2, const float* __restrict__ val_b2,
        const float* __restrict__ pol_w1, const float* __restrict__ pol_b1,
        const float* __restrict__ pol_w2, const float* __restrict__ pol_b2,
        float* __restrict__ out)
{
    extern __shared__ float sm[];
    float* B0  = sm + OFF_B0;
    float* B1  = sm + OFF_B1;
    float* FT  = sm + OFF_FT;
    float* sSm = sm + OFF_SM;
    int*   sAdj = reinterpret_cast<int*>(sm + OFF_ADJ);

    const int tid = threadIdx.x;
    const int b0  = blockIdx.x * BT;
    const int wid = tid >> 5, lane = tid & 31;

    // ---------- stage inputs (transposed) + small params ----------
    pf_l1(enc_w1, tid, OBS*HD);
    for (int idx = tid; idx < NROWS*OBS; idx += NTHREADS) {
        const int r = idx >> 6, k = idx & 63;
        const int lb = r / NNODE, n = r - lb*NNODE;
        const float v = (n == 0) ? obs[(size_t)(b0+lb)*OBS + k]
                                 : nobs[((size_t)(b0+lb)*NNB + (n-1))*OBS + k];
        B0[k*ATS + r] = v;
    }
    for (int idx = tid; idx < HD; idx += NTHREADS) {
        sSm[idx]        = enc_b1[idx];
        sSm[128 + idx]  = enc_b2[idx];
        sSm[768 + idx]  = val_b1[idx];
        sSm[896 + idx]  = val_w2[idx];
        sSm[1024 + idx] = pol_b1[idx];
    }
    for (int idx = tid; idx < 512;  idx += NTHREADS) sSm[256 + idx]  = gat_a[idx];
    for (int idx = tid; idx < 1024; idx += NTHREADS) sSm[1152 + idx] = pol_w2[idx];
    if (tid < NROWS) sAdj[tid] = adj[(size_t)b0*NNODE + tid];
    if (tid == 0) sSm[2256] = val_b2[0];
    if (tid < NACT) sSm[2257 + tid] = pol_b2[tid];
    __syncthreads();

    // ---------- encoder ----------
    gemmT<OBS, true >(B0, enc_w1, B1, sSm,        enc_w2, HD*HD, tid);  // hidden^T
    __syncthreads();
    gemmT<HD,  false>(B1, enc_w2, B0, sSm + 128,  gat_w,  HD*HD, tid);  // emb^T
    __syncthreads();

    // ---------- GAT heads ----------
    for (int h = 0; h < 2; h++) {
        const float* pfw = (h == 0) ? (gat_w + HD*HD) : val_w1;
        gemmT<HD, false>(B0, gat_w + h*HD*HD, B1, nullptr, pfw, HD*HD, tid);  // Wh^T
        __syncthreads();

        // attention: warp handles 2 batch elements
        #pragma unroll
        for (int q = 0; q < 2; q++) {
            const int lb = wid*2 + q;
            const float* a1 = sSm + 256 + h*256;
            const float* a2 = a1 + HD;
            float ei = 0.f, ej0 = 0.f, ej1 = 0.f, ej2 = 0.f, ej3 = 0.f, ej4 = 0.f;
            for (int kk = lane; kk < HD; kk += 32) {
                const float w1v = a1[kk], w2v = a2[kk];
                const float* whb = B1 + kk*ATS + lb*NNODE;
                const float v0 = whb[0], v1 = whb[1], v2 = whb[2],
                            v3 = whb[3], v4 = whb[4];
                ei  = fmaf(v0, w1v, ei);
                ej0 = fmaf(v0, w2v, ej0);
                ej1 = fmaf(v1, w2v, ej1);
                ej2 = fmaf(v2, w2v, ej2);
                ej3 = fmaf(v3, w2v, ej3);
                ej4 = fmaf(v4, w2v, ej4);
            }
            #pragma unroll
            for (int off = 16; off > 0; off >>= 1) {
                ei  += __shfl_xor_sync(0xffffffffu, ei,  off);
                ej0 += __shfl_xor_sync(0xffffffffu, ej0, off);
                ej1 += __shfl_xor_sync(0xffffffffu, ej1, off);
                ej2 += __shfl_xor_sync(0xffffffffu, ej2, off);
                ej3 += __shfl_xor_sync(0xffffffffu, ej3, off);
                ej4 += __shfl_xor_sync(0xffffffffu, ej4, off);
            }
            if (lane == 0) {
                float ej[5] = {ej0, ej1, ej2, ej3, ej4};
                float ev[5];
                float m = -1e30f;
                #pragma unroll
                for (int n = 0; n < NNODE; n++) {
                    if (sAdj[lb*NNODE + n] != 0) {
                        float e = ei + ej[n];
                        e = (e >= 0.f) ? e : SLOPE * e;
                        ev[n] = e;
                        m = fmaxf(m, e);
                    } else {
                        ev[n] = -1e30f;
                    }
                }
                float s = 0.f;
                #pragma unroll
                for (int n = 0; n < NNODE; n++) {
                    const float p = (ev[n] > -1e29f) ? __expf(ev[n] - m) : 0.f;
                    ev[n] = p; s += p;
                }
                const float inv = 1.f / s;
                #pragma unroll
                for (int n = 0; n < NNODE; n++) sSm[2176 + lb*NNODE + n] = ev[n] * inv;
            }
        }
        __syncthreads();

        // h_prime row 0 -> FT[(h*128+c)][lb]
        for (int idx = tid; idx < BT*HD; idx += NTHREADS) {
            const int lb = idx >> 7, c = idx & 127;
            const float* at  = sSm + 2176 + lb*NNODE;
            const float* whb = B1 + c*ATS + lb*NNODE;
            float s = at[0] * whb[0];
            s = fmaf(at[1], whb[1], s);
            s = fmaf(at[2], whb[2], s);
            s = fmaf(at[3], whb[3], s);
            s = fmaf(at[4], whb[4], s);
            FT[(h*HD + c)*FTS + lb] = s;
        }
        __syncthreads();
    }

    // ---------- fused value+policy first layers ----------
    // warps 0-3 -> value head, warps 4-7 -> policy head; 16 rows x 128 cols each.
    {
        const int head = wid >> 2;
        const float* Wg = head ? pol_w1 : val_w1;
        const float* bs = head ? (sSm + 1024) : (sSm + 768);
        float* H = head ? (B1 + BT*HD) : B1;   // hv=B1, hp=B1+2048
        const int rbase = (wid & 3) * 4 + (lane >> 4) * 2;  // even rows 0..14
        const int c0 = (lane & 15) * 8;

        u64 acc[2][4];
        #pragma unroll
        for (int r = 0; r < 2; r++)
            #pragma unroll
            for (int j = 0; j < 4; j++) acc[r][j] = 0ull;

        #pragma unroll 2
        for (int k = 0; k < 2*HD; k++) {
            const float2 a = *reinterpret_cast<const float2*>(FT + k*FTS + rbase);
            const u64 a0 = pack2(a.x, a.x), a1 = pack2(a.y, a.y);
            const ulonglong2 w0 = __ldg(reinterpret_cast<const ulonglong2*>(Wg + k*HD + c0));
            const ulonglong2 w1 = __ldg(reinterpret_cast<const ulonglong2*>(Wg + k*HD + c0 + 4));
            acc[0][0] = ffma2(a0, w0.x, acc[0][0]);
            acc[0][1] = ffma2(a0, w0.y, acc[0][1]);
            acc[0][2] = ffma2(a0, w1.x, acc[0][2]);
            acc[0][3] = ffma2(a0, w1.y, acc[0][3]);
            acc[1][0] = ffma2(a1, w0.x, acc[1][0]);
            acc[1][1] = ffma2(a1, w0.y, acc[1][1]);
            acc[1][2] = ffma2(a1, w1.x, acc[1][2]);
            acc[1][3] = ffma2(a1, w1.y, acc[1][3]);
        }
        #pragma unroll
        for (int r = 0; r < 2; r++)
            #pragma unroll
            for (int j = 0; j < 4; j++) {
                const int c = c0 + 2*j;
                float2 v = unpack2(acc[r][j]);
                v.x = fmaxf(v.x + bs[c],     0.f);
                v.y = fmaxf(v.y + bs[c + 1], 0.f);
                *reinterpret_cast<float2*>(H + (rbase + r)*HD + c) = v;
            }
    }
    __syncthreads();

    // ---------- value = hv @ val_w2 + b ----------
    #pragma unroll
    for (int q = 0; q < 2; q++) {
        const int lb = wid*2 + q;
        float s = 0.f;
        for (int kk = lane; kk < HD; kk += 32)
            s = fmaf(B1[lb*HD + kk], sSm[896 + kk], s);
        #pragma unroll
        for (int off = 16; off > 0; off >>= 1) s += __shfl_xor_sync(0xffffffffu, s, off);
        if (lane == 0) out[b0 + lb] = s + sSm[2256];
    }

    // ---------- logits = hp @ pol_w2 + b ----------
    if (tid < BT*NACT) {
        const int lb = tid >> 3, a = tid & 7;
        const float* hp = B1 + BT*HD + lb*HD;
        float s = 0.f;
        for (int kk = 0; kk < HD; kk++)
            s = fmaf(hp[kk], sSm[1152 + kk*NACT + a], s);
        out[NB + (size_t)(b0+lb)*NACT + a] = s + sSm[2257 + a];
    }
}

extern "C" void kernel_launch(void* const* d_in, const int* in_sizes, int n_in,
                              void* d_out, int out_size)
{
    (void)in_sizes; (void)n_in; (void)out_size;
    cudaFuncSetAttribute(colight, cudaFuncAttributeMaxDynamicSharedMemorySize, SMEM_BYTES);
    colight<<<NB/BT, NTHREADS, SMEM_BYTES>>>(
        (const float*)d_in[0],  (const float*)d_in[1],  (const int*)d_in[2],
        (const float*)d_in[3],  (const float*)d_in[4],  (const float*)d_in[5],
        (const float*)d_in[6],  (const float*)d_in[7],  (const float*)d_in[8],
        (const float*)d_in[9],  (const float*)d_in[10], (const float*)d_in[11],
        (const float*)d_in[12], (const float*)d_in[13], (const float*)d_in[14],
        (const float*)d_in[15], (const float*)d_in[16],
        (float*)d_out);
}

// round 3
// speedup vs baseline: 1.1295x; 1.0003x over previous
#include <cuda_runtime.h>

#define NB      16384
#define OBS     64
#define HD      128
#define NNB     4
#define NNODE   5
#define NACT    8
#define SLOPE   0.2f
#define BT      16
#define NTHREADS 256
#define NROWS   (BT*NNODE)   // 80
#define ATS     82           // padded stride for transposed activations (even, ~coprime to 32)
#define FTS     18           // padded stride for final^T [256][16+pad]

typedef unsigned long long u64;

// ---- smem layout (float offsets) ----
#define OFF_B0  0
#define SZ_B0   (HD*ATS)          // 10496
#define OFF_B1  (OFF_B0 + SZ_B0)
#define SZ_B1   (HD*ATS)          // 10496
#define OFF_FT  (OFF_B1 + SZ_B1)
#define SZ_FT   (2*HD*FTS)        // 4608
#define OFF_SM  (OFF_FT + SZ_FT)
// 0 enc_b1[128], 128 enc_b2[128], 256 gat_a[512], 768 val_b1[128],
// 896 val_w2[128], 1024 pol_b1[128], 1152 pol_w2[1024], 2176 attn[80],
// 2256 val_b2, 2257..2264 pol_b2
#define SZ_SM   2272
#define OFF_ADJ (OFF_SM + SZ_SM)  // 80 ints
#define SMEM_FLOATS (OFF_ADJ + 80)
#define SMEM_BYTES  (SMEM_FLOATS*4)

__device__ __forceinline__ u64 ffma2(u64 a, u64 b, u64 c) {
    u64 d;
    asm("fma.rn.f32x2 %0, %1, %2, %3;" : "=l"(d) : "l"(a), "l"(b), "l"(c));
    return d;
}
__device__ __forceinline__ u64 pack2(float x, float y) {
    u64 r; asm("mov.b64 %0, {%1, %2};" : "=l"(r) : "f"(x), "f"(y)); return r;
}
__device__ __forceinline__ float2 unpack2(u64 v) {
    float2 r; asm("mov.b64 {%0, %1}, %2;" : "=f"(r.x), "=f"(r.y) : "l"(v)); return r;
}

// Prefetch nfloats of gmem into L1 (128B lines, strided over the CTA).
__device__ __forceinline__ void pf_l1(const float* p, int tid, int nfloats) {
    for (int off = tid * 32; off < nfloats; off += NTHREADS * 32)
        asm volatile("prefetch.global.L1 [%0];" :: "l"(p + off));
}

// C^T[128][ATS] = (A^T[K][ATS])-gemm: C[r][c] = sum_k A[r][k]*W[k][c] (+bias)(relu).
// A^T in smem (AT[k*ATS + r]); W row-major [K][128] in GLOBAL (read via L1).
// Per-thread tile: 5 row-pairs x 4 cols, f32x2 lanes = (row, row+1).
template<int K, bool RELU>
__device__ __forceinline__ void gemmT(const float* __restrict__ AT,
                                      const float* __restrict__ Wg,
                                      float* __restrict__ CT,
                                      const float* bias,          // smem or nullptr
                                      const float* __restrict__ pf, int pfN,
                                      int tid)
{
    const int tx = tid & 31, ty = tid >> 5;
    const int c0 = tx * 4, r0 = ty * 10;

    if (pf) pf_l1(pf, tid, pfN);

    u64 acc[5][4];
    #pragma unroll
    for (int p = 0; p < 5; p++)
        #pragma unroll
        for (int j = 0; j < 4; j++) acc[p][j] = 0ull;

    #pragma unroll 2
    for (int k = 0; k < K; k++) {
        const float4 w4 = __ldg(reinterpret_cast<const float4*>(Wg + k*HD + c0));
        const u64 w0 = pack2(w4.x, w4.x), w1 = pack2(w4.y, w4.y),
                  w2 = pack2(w4.z, w4.z), w3 = pack2(w4.w, w4.w);
        const float* a = AT + k*ATS + r0;
        u64 a2[5];
        #pragma unroll
        for (int p = 0; p < 5; p++)
            a2[p] = *reinterpret_cast<const u64*>(a + 2*p);
        #pragma unroll
        for (int p = 0; p < 5; p++) {
            acc[p][0] = ffma2(a2[p], w0, acc[p][0]);
            acc[p][1] = ffma2(a2[p], w1, acc[p][1]);
            acc[p][2] = ffma2(a2[p], w2, acc[p][2]);
            acc[p][3] = ffma2(a2[p], w3, acc[p][3]);
        }
    }
    #pragma unroll
    for (int j = 0; j < 4; j++) {
        const float b = bias ? bias[c0 + j] : 0.f;
        #pragma unroll
        for (int p = 0; p < 5; p++) {
            float2 v = unpack2(acc[p][j]);
            v.x += b; v.y += b;
            if (RELU) { v.x = fmaxf(v.x, 0.f); v.y = fmaxf(v.y, 0.f); }
            *reinterpret_cast<float2*>(CT + (c0 + j)*ATS + r0 + 2*p) = v;
        }
    }
}

extern "C" __global__ void __launch_bounds__(NTHREADS, 1)
colight(const float* __restrict__ obs, const float* __restrict__ nobs,
        const int* __restrict__ adj,
        const float* __restrict__ enc_w1, const float* __restrict__ enc_b1,
        const float* __restrict__ enc_w2, const float* __restrict__ enc_b2,
        const float* __restrict__ gat_w, const float* __restrict__ gat_a,
        const float* __restrict__ val_w1, const float* __restrict__ val_b1,
        const float* __restrict__ val_w2, const float* __restrict__ val_b2,
        const float* __restrict__ pol_w1, const float* __restrict__ pol_b1,
        const float* __restrict__ pol_w2, const float* __restrict__ pol_b2,
        float* __restrict__ out)
{
    extern __shared__ float sm[];
    float* B0  = sm + OFF_B0;
    float* B1  = sm + OFF_B1;
    float* FT  = sm + OFF_FT;
    float* sSm = sm + OFF_SM;
    int*   sAdj = reinterpret_cast<int*>(sm + OFF_ADJ);

    const int tid = threadIdx.x;
    const int b0  = blockIdx.x * BT;
    const int wid = tid >> 5, lane = tid & 31;

    // ---------- stage inputs (transposed) + small params ----------
    pf_l1(enc_w1, tid, OBS*HD);
    for (int idx = tid; idx < NROWS*OBS; idx += NTHREADS) {
        const int r = idx >> 6, k = idx & 63;
        const int lb = r / NNODE, n = r - lb*NNODE;
        const float v = (n == 0) ? obs[(size_t)(b0+lb)*OBS + k]
                                 : nobs[((size_t)(b0+lb)*NNB + (n-1))*OBS + k];
        B0[k*ATS + r] = v;
    }
    for (int idx = tid; idx < HD; idx += NTHREADS) {
        sSm[idx]        = enc_b1[idx];
        sSm[128 + idx]  = enc_b2[idx];
        sSm[768 + idx]  = val_b1[idx];
        sSm[896 + idx]  = val_w2[idx];
        sSm[1024 + idx] = pol_b1[idx];
    }
    for (int idx = tid; idx < 512;  idx += NTHREADS) sSm[256 + idx]  = gat_a[idx];
    for (int idx = tid; idx < 1024; idx += NTHREADS) sSm[1152 + idx] = pol_w2[idx];
    if (tid < NROWS) sAdj[tid] = adj[(size_t)b0*NNODE + tid];
    if (tid == 0) sSm[2256] = val_b2[0];
    if (tid < NACT) sSm[2257 + tid] = pol_b2[tid];
    __syncthreads();

    // ---------- encoder ----------
    gemmT<OBS, true >(B0, enc_w1, B1, sSm,        enc_w2, HD*HD, tid);  // hidden^T
    __syncthreads();
    gemmT<HD,  false>(B1, enc_w2, B0, sSm + 128,  gat_w,  HD*HD, tid);  // emb^T
    __syncthreads();

    // ---------- GAT heads ----------
    for (int h = 0; h < 2; h++) {
        const float* pfw = (h == 0) ? (gat_w + HD*HD) : val_w1;
        gemmT<HD, false>(B0, gat_w + h*HD*HD, B1, nullptr, pfw, HD*HD, tid);  // Wh^T
        __syncthreads();

        // attention: warp handles 2 batch elements
        #pragma unroll
        for (int q = 0; q < 2; q++) {
            const int lb = wid*2 + q;
            const float* a1 = sSm + 256 + h*256;
            const float* a2 = a1 + HD;
            float ei = 0.f, ej0 = 0.f, ej1 = 0.f, ej2 = 0.f, ej3 = 0.f, ej4 = 0.f;
            for (int kk = lane; kk < HD; kk += 32) {
                const float w1v = a1[kk], w2v = a2[kk];
                const float* whb = B1 + kk*ATS + lb*NNODE;
                const float v0 = whb[0], v1 = whb[1], v2 = whb[2],
                            v3 = whb[3], v4 = whb[4];
                ei  = fmaf(v0, w1v, ei);
                ej0 = fmaf(v0, w2v, ej0);
                ej1 = fmaf(v1, w2v, ej1);
                ej2 = fmaf(v2, w2v, ej2);
                ej3 = fmaf(v3, w2v, ej3);
                ej4 = fmaf(v4, w2v, ej4);
            }
            #pragma unroll
            for (int off = 16; off > 0; off >>= 1) {
                ei  += __shfl_xor_sync(0xffffffffu, ei,  off);
                ej0 += __shfl_xor_sync(0xffffffffu, ej0, off);
                ej1 += __shfl_xor_sync(0xffffffffu, ej1, off);
                ej2 += __shfl_xor_sync(0xffffffffu, ej2, off);
                ej3 += __shfl_xor_sync(0xffffffffu, ej3, off);
                ej4 += __shfl_xor_sync(0xffffffffu, ej4, off);
            }
            if (lane == 0) {
                float ej[5] = {ej0, ej1, ej2, ej3, ej4};
                float ev[5];
                float m = -1e30f;
                #pragma unroll
                for (int n = 0; n < NNODE; n++) {
                    if (sAdj[lb*NNODE + n] != 0) {
                        float e = ei + ej[n];
                        e = (e >= 0.f) ? e : SLOPE * e;
                        ev[n] = e;
                        m = fmaxf(m, e);
                    } else {
                        ev[n] = -1e30f;
                    }
                }
                float s = 0.f;
                #pragma unroll
                for (int n = 0; n < NNODE; n++) {
                    const float p = (ev[n] > -1e29f) ? __expf(ev[n] - m) : 0.f;
                    ev[n] = p; s += p;
                }
                const float inv = 1.f / s;
                #pragma unroll
                for (int n = 0; n < NNODE; n++) sSm[2176 + lb*NNODE + n] = ev[n] * inv;
            }
        }
        __syncthreads();

        // h_prime row 0 -> FT[(h*128+c)][lb]
        for (int idx = tid; idx < BT*HD; idx += NTHREADS) {
            const int lb = idx >> 7, c = idx & 127;
            const float* at  = sSm + 2176 + lb*NNODE;
            const float* whb = B1 + c*ATS + lb*NNODE;
            float s = at[0] * whb[0];
            s = fmaf(at[1], whb[1], s);
            s = fmaf(at[2], whb[2], s);
            s = fmaf(at[3], whb[3], s);
            s = fmaf(at[4], whb[4], s);
            FT[(h*HD + c)*FTS + lb] = s;
        }
        __syncthreads();
    }

    // ---------- fused value+policy first layers ----------
    // warps 0-3 -> value head, warps 4-7 -> policy head; 16 rows x 128 cols each.
    {
        const int head = wid >> 2;
        const float* Wg = head ? pol_w1 : val_w1;
        const float* bs = head ? (sSm + 1024) : (sSm + 768);
        float* H = head ? (B1 + BT*HD) : B1;   // hv=B1, hp=B1+2048
        const int rbase = (wid & 3) * 4 + (lane >> 4) * 2;  // even rows 0..14
        const int c0 = (lane & 15) * 8;

        u64 acc[2][4];
        #pragma unroll
        for (int r = 0; r < 2; r++)
            #pragma unroll
            for (int j = 0; j < 4; j++) acc[r][j] = 0ull;

        #pragma unroll 2
        for (int k = 0; k < 2*HD; k++) {
            const float2 a = *reinterpret_cast<const float2*>(FT + k*FTS + rbase);
            const u64 a0 = pack2(a.x, a.x), a1 = pack2(a.y, a.y);
            const ulonglong2 w0 = __ldg(reinterpret_cast<const ulonglong2*>(Wg + k*HD + c0));
            const ulonglong2 w1 = __ldg(reinterpret_cast<const ulonglong2*>(Wg + k*HD + c0 + 4));
            acc[0][0] = ffma2(a0, w0.x, acc[0][0]);
            acc[0][1] = ffma2(a0, w0.y, acc[0][1]);
            acc[0][2] = ffma2(a0, w1.x, acc[0][2]);
            acc[0][3] = ffma2(a0, w1.y, acc[0][3]);
            acc[1][0] = ffma2(a1, w0.x, acc[1][0]);
            acc[1][1] = ffma2(a1, w0.y, acc[1][1]);
            acc[1][2] = ffma2(a1, w1.x, acc[1][2]);
            acc[1][3] = ffma2(a1, w1.y, acc[1][3]);
        }
        #pragma unroll
        for (int r = 0; r < 2; r++)
            #pragma unroll
            for (int j = 0; j < 4; j++) {
                const int c = c0 + 2*j;
                float2 v = unpack2(acc[r][j]);
                v.x = fmaxf(v.x + bs[c],     0.f);
                v.y = fmaxf(v.y + bs[c + 1], 0.f);
                *reinterpret_cast<float2*>(H + (rbase + r)*HD + c) = v;
            }
    }
    __syncthreads();

    // ---------- value = hv @ val_w2 + b ----------
    #pragma unroll
    for (int q = 0; q < 2; q++) {
        const int lb = wid*2 + q;
        float s = 0.f;
        for (int kk = lane; kk < HD; kk += 32)
            s = fmaf(B1[lb*HD + kk], sSm[896 + kk], s);
        #pragma unroll
        for (int off = 16; off > 0; off >>= 1) s += __shfl_xor_sync(0xffffffffu, s, off);
        if (lane == 0) out[b0 + lb] = s + sSm[2256];
    }

    // ---------- logits = hp @ pol_w2 + b ----------
    if (tid < BT*NACT) {
        const int lb = tid >> 3, a = tid & 7;
        const float* hp = B1 + BT*HD + lb*HD;
        float s = 0.f;
        for (int kk = 0; kk < HD; kk++)
            s = fmaf(hp[kk], sSm[1152 + kk*NACT + a], s);
        out[NB + (size_t)(b0+lb)*NACT + a] = s + sSm[2257 + a];
    }
}

extern "C" void kernel_launch(void* const* d_in, const int* in_sizes, int n_in,
                              void* d_out, int out_size)
{
    (void)in_sizes; (void)n_in; (void)out_size;
    cudaFuncSetAttribute(colight, cudaFuncAttributeMaxDynamicSharedMemorySize, SMEM_BYTES);
    colight<<<NB/BT, NTHREADS, SMEM_BYTES>>>(
        (const float*)d_in[0],  (const float*)d_in[1],  (const int*)d_in[2],
        (const float*)d_in[3],  (const float*)d_in[4],  (const float*)d_in[5],
        (const float*)d_in[6],  (const float*)d_in[7],  (const float*)d_in[8],
        (const float*)d_in[9],  (const float*)d_in[10], (const float*)d_in[11],
        (const float*)d_in[12], (const float*)d_in[13], (const float*)d_in[14],
        (const float*)d_in[15], (const float*)d_in[16],
        (float*)d_out);
}

// round 5
// speedup vs baseline: 1.3904x; 1.2310x over previous
#include <cuda_runtime.h>

#define NB      16384
#define OBS     64
#define HD      128
#define NNB     4
#define NNODE   5
#define NACT    8
#define SLOPE   0.2f
#define BT      16
#define NTHREADS 256
#define NROWS   (BT*NNODE)   // 80
#define ATS     82           // padded stride for transposed activations
#define FTS     18           // padded stride for final^T [256][16+pad]

typedef unsigned long long u64;

// ---- smem layout (float offsets) ----
#define OFF_B0  0
#define SZ_B0   (HD*ATS)          // 10496
#define OFF_B1  (OFF_B0 + SZ_B0)
#define SZ_B1   (HD*ATS)          // 10496
#define OFF_FT  (OFF_B1 + SZ_B1)
#define SZ_FT   (2*HD*FTS)        // 4608
#define OFF_SM  (OFF_FT + SZ_FT)
// 0 enc_b1[128], 128 enc_b2[128], 256 gat_a[512], 768 val_b1[128],
// 896 val_w2[128], 1024 pol_b1[128], 1152 pol_w2[1024], 2176 attn[80],
// 2256 val_b2, 2257..2264 pol_b2
#define SZ_SM   2272
#define OFF_ADJ (OFF_SM + SZ_SM)  // 80 ints
#define SMEM_FLOATS (OFF_ADJ + 80)
#define SMEM_BYTES  (SMEM_FLOATS*4)   // 111808 B -> 2 CTAs/SM (2x(109.2K+1K) <= 228K)

__device__ __forceinline__ u64 ffma2(u64 a, u64 b, u64 c) {
    u64 d;
    asm("fma.rn.f32x2 %0, %1, %2, %3;" : "=l"(d) : "l"(a), "l"(b), "l"(c));
    return d;
}
__device__ __forceinline__ u64 pack2(float x, float y) {
    u64 r; asm("mov.b64 %0, {%1, %2};" : "=l"(r) : "f"(x), "f"(y)); return r;
}
__device__ __forceinline__ float2 unpack2(u64 v) {
    float2 r; asm("mov.b64 {%0, %1}, %2;" : "=f"(r.x), "=f"(r.y) : "l"(v)); return r;
}

// Prefetch nfloats of gmem into L2 (weights won't fit L1D at 2 CTAs/SM).
__device__ __forceinline__ void pf_l2(const float* p, int tid, int nfloats) {
    for (int off = tid * 32; off < nfloats; off += NTHREADS * 32)
        asm volatile("prefetch.global.L2 [%0];" :: "l"(p + off));
}

// C^T[128][ATS]: C[r][c] = sum_k A[r][k]*W[k][c] (+bias)(relu).
// A^T in smem; W row-major [K][128] in GLOBAL (L2-resident).
// Per-thread tile: 5 row-pairs x 4 cols, f32x2 lanes = (row, row+1).
template<int K, bool RELU>
__device__ __forceinline__ void gemmT(const float* __restrict__ AT,
                                      const float* __restrict__ Wg,
                                      float* __restrict__ CT,
                                      const float* bias,          // smem or nullptr
                                      const float* __restrict__ pf, int pfN,
                                      int tid)
{
    const int tx = tid & 31, ty = tid >> 5;
    const int c0 = tx * 4, r0 = ty * 10;

    if (pf) pf_l2(pf, tid, pfN);

    u64 acc[5][4];
    #pragma unroll
    for (int p = 0; p < 5; p++)
        #pragma unroll
        for (int j = 0; j < 4; j++) acc[p][j] = 0ull;

    #pragma unroll 4
    for (int k = 0; k < K; k++) {
        const float4 w4 = __ldg(reinterpret_cast<const float4*>(Wg + k*HD + c0));
        const u64 w0 = pack2(w4.x, w4.x), w1 = pack2(w4.y, w4.y),
                  w2 = pack2(w4.z, w4.z), w3 = pack2(w4.w, w4.w);
        const float* a = AT + k*ATS + r0;
        u64 a2[5];
        #pragma unroll
        for (int p = 0; p < 5; p++)
            a2[p] = *reinterpret_cast<const u64*>(a + 2*p);
        #pragma unroll
        for (int p = 0; p < 5; p++) {
            acc[p][0] = ffma2(a2[p], w0, acc[p][0]);
            acc[p][1] = ffma2(a2[p], w1, acc[p][1]);
            acc[p][2] = ffma2(a2[p], w2, acc[p][2]);
            acc[p][3] = ffma2(a2[p], w3, acc[p][3]);
        }
    }
    #pragma unroll
    for (int j = 0; j < 4; j++) {
        const float b = bias ? bias[c0 + j] : 0.f;
        #pragma unroll
        for (int p = 0; p < 5; p++) {
            float2 v = unpack2(acc[p][j]);
            v.x += b; v.y += b;
            if (RELU) { v.x = fmaxf(v.x, 0.f); v.y = fmaxf(v.y, 0.f); }
            *reinterpret_cast<float2*>(CT + (c0 + j)*ATS + r0 + 2*p) = v;
        }
    }
}

extern "C" __global__ void __launch_bounds__(NTHREADS, 2)
colight(const float* __restrict__ obs, const float* __restrict__ nobs,
        const int* __restrict__ adj,
        const float* __restrict__ enc_w1, const float* __restrict__ enc_b1,
        const float* __restrict__ enc_w2, const float* __restrict__ enc_b2,
        const float* __restrict__ gat_w, const float* __restrict__ gat_a,
        const float* __restrict__ val_w1, const float* __restrict__ val_b1,
        const float* __restrict__ val_w2, const float* __restrict__ val_b2,
        const float* __restrict__ pol_w1, const float* __restrict__ pol_b1,
        const float* __restrict__ pol_w2, const float* __restrict__ pol_b2,
        float* __restrict__ out)
{
    extern __shared__ float sm[];
    float* B0  = sm + OFF_B0;
    float* B1  = sm + OFF_B1;
    float* FT  = sm + OFF_FT;
    float* sSm = sm + OFF_SM;
    int*   sAdj = reinterpret_cast<int*>(sm + OFF_ADJ);

    const int tid = threadIdx.x;
    const int b0  = blockIdx.x * BT;
    const int wid = tid >> 5, lane = tid & 31;

    // ---------- stage inputs (transposed) + small params ----------
    pf_l2(enc_w1, tid, OBS*HD);
    for (int idx = tid; idx < NROWS*OBS; idx += NTHREADS) {
        const int r = idx >> 6, k = idx & 63;
        const int lb = r / NNODE, n = r - lb*NNODE;
        const float v = (n == 0) ? obs[(size_t)(b0+lb)*OBS + k]
                                 : nobs[((size_t)(b0+lb)*NNB + (n-1))*OBS + k];
        B0[k*ATS + r] = v;
    }
    for (int idx = tid; idx < HD; idx += NTHREADS) {
        sSm[idx]        = enc_b1[idx];
        sSm[128 + idx]  = enc_b2[idx];
        sSm[768 + idx]  = val_b1[idx];
        sSm[896 + idx]  = val_w2[idx];
        sSm[1024 + idx] = pol_b1[idx];
    }
    for (int idx = tid; idx < 512;  idx += NTHREADS) sSm[256 + idx]  = gat_a[idx];
    for (int idx = tid; idx < 1024; idx += NTHREADS) sSm[1152 + idx] = pol_w2[idx];
    if (tid < NROWS) sAdj[tid] = adj[(size_t)b0*NNODE + tid];
    if (tid == 0) sSm[2256] = val_b2[0];
    if (tid < NACT) sSm[2257 + tid] = pol_b2[tid];
    __syncthreads();

    // ---------- encoder ----------
    gemmT<OBS, true >(B0, enc_w1, B1, sSm,        enc_w2, HD*HD, tid);  // hidden^T
    __syncthreads();
    gemmT<HD,  false>(B1, enc_w2, B0, sSm + 128,  gat_w,  HD*HD, tid);  // emb^T
    __syncthreads();

    // ---------- GAT heads ----------
    for (int h = 0; h < 2; h++) {
        const float* pfw = (h == 0) ? (gat_w + HD*HD) : val_w1;
        gemmT<HD, false>(B0, gat_w + h*HD*HD, B1, nullptr, pfw, HD*HD, tid);  // Wh^T
        __syncthreads();

        // attention: warp handles 2 batch elements
        #pragma unroll
        for (int q = 0; q < 2; q++) {
            const int lb = wid*2 + q;
            const float* a1 = sSm + 256 + h*256;
            const float* a2 = a1 + HD;
            float ei = 0.f, ej0 = 0.f, ej1 = 0.f, ej2 = 0.f, ej3 = 0.f, ej4 = 0.f;
            for (int kk = lane; kk < HD; kk += 32) {
                const float w1v = a1[kk], w2v = a2[kk];
                const float* whb = B1 + kk*ATS + lb*NNODE;
                const float v0 = whb[0], v1 = whb[1], v2 = whb[2],
                            v3 = whb[3], v4 = whb[4];
                ei  = fmaf(v0, w1v, ei);
                ej0 = fmaf(v0, w2v, ej0);
                ej1 = fmaf(v1, w2v, ej1);
                ej2 = fmaf(v2, w2v, ej2);
                ej3 = fmaf(v3, w2v, ej3);
                ej4 = fmaf(v4, w2v, ej4);
            }
            #pragma unroll
            for (int off = 16; off > 0; off >>= 1) {
                ei  += __shfl_xor_sync(0xffffffffu, ei,  off);
                ej0 += __shfl_xor_sync(0xffffffffu, ej0, off);
                ej1 += __shfl_xor_sync(0xffffffffu, ej1, off);
                ej2 += __shfl_xor_sync(0xffffffffu, ej2, off);
                ej3 += __shfl_xor_sync(0xffffffffu, ej3, off);
                ej4 += __shfl_xor_sync(0xffffffffu, ej4, off);
            }
            if (lane == 0) {
                float ej[5] = {ej0, ej1, ej2, ej3, ej4};
                float ev[5];
                float m = -1e30f;
                #pragma unroll
                for (int n = 0; n < NNODE; n++) {
                    if (sAdj[lb*NNODE + n] != 0) {
                        float e = ei + ej[n];
                        e = (e >= 0.f) ? e : SLOPE * e;
                        ev[n] = e;
                        m = fmaxf(m, e);
                    } else {
                        ev[n] = -1e30f;
                    }
                }
                float s = 0.f;
                #pragma unroll
                for (int n = 0; n < NNODE; n++) {
                    const float p = (ev[n] > -1e29f) ? __expf(ev[n] - m) : 0.f;
                    ev[n] = p; s += p;
                }
                const float inv = 1.f / s;
                #pragma unroll
                for (int n = 0; n < NNODE; n++) sSm[2176 + lb*NNODE + n] = ev[n] * inv;
            }
        }
        __syncthreads();

        // h_prime row 0 -> FT[(h*128+c)][lb]
        for (int idx = tid; idx < BT*HD; idx += NTHREADS) {
            const int lb = idx >> 7, c = idx & 127;
            const float* at  = sSm + 2176 + lb*NNODE;
            const float* whb = B1 + c*ATS + lb*NNODE;
            float s = at[0] * whb[0];
            s = fmaf(at[1], whb[1], s);
            s = fmaf(at[2], whb[2], s);
            s = fmaf(at[3], whb[3], s);
            s = fmaf(at[4], whb[4], s);
            FT[(h*HD + c)*FTS + lb] = s;
        }
        __syncthreads();
    }

    // ---------- fused value+policy first layers ----------
    // warps 0-3 -> value head, warps 4-7 -> policy head; 16 rows x 128 cols each.
    {
        const int head = wid >> 2;
        const float* Wg = head ? pol_w1 : val_w1;
        const float* bs = head ? (sSm + 1024) : (sSm + 768);
        float* H = head ? (B1 + BT*HD) : B1;   // hv=B1, hp=B1+2048
        const int rbase = (wid & 3) * 4 + (lane >> 4) * 2;  // even rows 0..14
        const int c0 = (lane & 15) * 8;

        u64 acc[2][4];
        #pragma unroll
        for (int r = 0; r < 2; r++)
            #pragma unroll
            for (int j = 0; j < 4; j++) acc[r][j] = 0ull;

        #pragma unroll 4
        for (int k = 0; k < 2*HD; k++) {
            const float2 a = *reinterpret_cast<const float2*>(FT + k*FTS + rbase);
            const u64 a0 = pack2(a.x, a.x), a1 = pack2(a.y, a.y);
            const ulonglong2 w0 = __ldg(reinterpret_cast<const ulonglong2*>(Wg + k*HD + c0));
            const ulonglong2 w1 = __ldg(reinterpret_cast<const ulonglong2*>(Wg + k*HD + c0 + 4));
            acc[0][0] = ffma2(a0, w0.x, acc[0][0]);
            acc[0][1] = ffma2(a0, w0.y, acc[0][1]);
            acc[0][2] = ffma2(a0, w1.x, acc[0][2]);
            acc[0][3] = ffma2(a0, w1.y, acc[0][3]);
            acc[1][0] = ffma2(a1, w0.x, acc[1][0]);
            acc[1][1] = ffma2(a1, w0.y, acc[1][1]);
            acc[1][2] = ffma2(a1, w1.x, acc[1][2]);
            acc[1][3] = ffma2(a1, w1.y, acc[1][3]);
        }
        #pragma unroll
        for (int r = 0; r < 2; r++)
            #pragma unroll
            for (int j = 0; j < 4; j++) {
                const int c = c0 + 2*j;
                float2 v = unpack2(acc[r][j]);
                v.x = fmaxf(v.x + bs[c],     0.f);
                v.y = fmaxf(v.y + bs[c + 1], 0.f);
                *reinterpret_cast<float2*>(H + (rbase + r)*HD + c) = v;
            }
    }
    __syncthreads();

    // ---------- value = hv @ val_w2 + b ----------
    #pragma unroll
    for (int q = 0; q < 2; q++) {
        const int lb = wid*2 + q;
        float s = 0.f;
        for (int kk = lane; kk < HD; kk += 32)
            s = fmaf(B1[lb*HD + kk], sSm[896 + kk], s);
        #pragma unroll
        for (int off = 16; off > 0; off >>= 1) s += __shfl_xor_sync(0xffffffffu, s, off);
        if (lane == 0) out[b0 + lb] = s + sSm[2256];
    }

    // ---------- logits = hp @ pol_w2 + b ----------
    if (tid < BT*NACT) {
        const int lb = tid >> 3, a = tid & 7;
        const float* hp = B1 + BT*HD + lb*HD;
        float s = 0.f;
        for (int kk = 0; kk < HD; kk++)
            s = fmaf(hp[kk], sSm[1152 + kk*NACT + a], s);
        out[NB + (size_t)(b0+lb)*NACT + a] = s + sSm[2257 + a];
    }
}

extern "C" void kernel_launch(void* const* d_in, const int* in_sizes, int n_in,
                              void* d_out, int out_size)
{
    (void)in_sizes; (void)n_in; (void)out_size;
    cudaFuncSetAttribute(colight, cudaFuncAttributeMaxDynamicSharedMemorySize, SMEM_BYTES);
    colight<<<NB/BT, NTHREADS, SMEM_BYTES>>>(
        (const float*)d_in[0],  (const float*)d_in[1],  (const int*)d_in[2],
        (const float*)d_in[3],  (const float*)d_in[4],  (const float*)d_in[5],
        (const float*)d_in[6],  (const float*)d_in[7],  (const float*)d_in[8],
        (const float*)d_in[9],  (const float*)d_in[10], (const float*)d_in[11],
        (const float*)d_in[12], (const float*)d_in[13], (const float*)d_in[14],
        (const float*)d_in[15], (const float*)d_in[16],
        (float*)d_out);
}